// round 2
// baseline (speedup 1.0000x reference)
#include <cuda_runtime.h>

// Fixed problem shape (from reference setup_inputs): B=4, H=W=256, DIM=192, NH=6, HD=32, WS=8
// tokens = B*65536, windows = B*1024, window tokens T=64.

__device__ float g_qkv[150994944];   // B*65536*576  (qkv scratch, 603 MB)
__device__ float g_o[50331648];      // B*65536*192  (attention output scratch, 201 MB)

// ---------------- packed f32x2 helpers (FFMA2 path, sm_103a) ----------------
__device__ __forceinline__ unsigned long long pack2(float lo, float hi) {
    unsigned long long r;
    asm("mov.b64 %0, {%1, %2};" : "=l"(r) : "f"(lo), "f"(hi));
    return r;
}
__device__ __forceinline__ void unpack2(unsigned long long v, float& lo, float& hi) {
    asm("mov.b64 {%0, %1}, %2;" : "=f"(lo), "=f"(hi) : "l"(v));
}
__device__ __forceinline__ void ffma2(unsigned long long& d, unsigned long long a, unsigned long long b) {
    asm("fma.rn.f32x2 %0, %1, %2, %0;" : "+l"(d) : "l"(a), "l"(b));
}

// ---------------- GEMM: C[M,N] = A[M,K] @ W[N,K]^T + bias ----------------
// Tile 128(M) x 64(N), K-chunk 16, 128 threads, 8x8 micro-tile per thread.
// Inner loop: 4 LDS.128 (2048B/warp) vs 32 FFMA2 per kk -> balanced on B300.
__global__ __launch_bounds__(128) void gemm_kernel(
    const float* __restrict__ A, const float* __restrict__ W,
    const float* __restrict__ bias, float* __restrict__ C,
    int M, int N, int K)
{
    __shared__ float As[16][132];
    __shared__ float Bs[16][68];

    const int tid = threadIdx.x;
    const int bm = blockIdx.y * 128;
    const int bn = blockIdx.x * 64;
    const int tx = tid & 7;    // n-dir, 8 cols
    const int ty = tid >> 3;   // m-dir, 8 rows

    unsigned long long acc[4][8];   // pairs over m: acc[i2][j] = (row 2*i2, row 2*i2+1)
#pragma unroll
    for (int i = 0; i < 4; i++)
#pragma unroll
        for (int j = 0; j < 8; j++) acc[i][j] = pack2(0.f, 0.f);

    float bvals[8];
#pragma unroll
    for (int j = 0; j < 8; j++) bvals[j] = bias[bn + tx * 8 + j];

    for (int k0 = 0; k0 < K; k0 += 16) {
        // load A tile 128x16 (512 float4, 4 per thread), stored transposed As[k][m]
#pragma unroll
        for (int i = 0; i < 4; i++) {
            int lin = tid + i * 128;
            int row = lin >> 2, kq = lin & 3;
            float4 v = *(const float4*)&A[(size_t)(bm + row) * K + k0 + kq * 4];
            As[kq * 4 + 0][row] = v.x;
            As[kq * 4 + 1][row] = v.y;
            As[kq * 4 + 2][row] = v.z;
            As[kq * 4 + 3][row] = v.w;
        }
        // load W tile 64x16 (256 float4, 2 per thread), stored transposed Bs[k][n]
#pragma unroll
        for (int i = 0; i < 2; i++) {
            int lin = tid + i * 128;
            int row = lin >> 2, kq = lin & 3;
            float4 v = *(const float4*)&W[(size_t)(bn + row) * K + k0 + kq * 4];
            Bs[kq * 4 + 0][row] = v.x;
            Bs[kq * 4 + 1][row] = v.y;
            Bs[kq * 4 + 2][row] = v.z;
            Bs[kq * 4 + 3][row] = v.w;
        }
        __syncthreads();

#pragma unroll
        for (int kk = 0; kk < 16; kk++) {
            float a[8], b[8];
            *(float4*)&a[0] = *(const float4*)&As[kk][ty * 8];
            *(float4*)&a[4] = *(const float4*)&As[kk][ty * 8 + 4];
            *(float4*)&b[0] = *(const float4*)&Bs[kk][tx * 8];
            *(float4*)&b[4] = *(const float4*)&Bs[kk][tx * 8 + 4];
            unsigned long long ap[4];
            ap[0] = pack2(a[0], a[1]);
            ap[1] = pack2(a[2], a[3]);
            ap[2] = pack2(a[4], a[5]);
            ap[3] = pack2(a[6], a[7]);
#pragma unroll
            for (int j = 0; j < 8; j++) {
                unsigned long long bd = pack2(b[j], b[j]);
#pragma unroll
                for (int i = 0; i < 4; i++) ffma2(acc[i][j], ap[i], bd);
            }
        }
        __syncthreads();
    }

    // write out 8x8 micro-tile with bias
#pragma unroll
    for (int i2 = 0; i2 < 4; i2++) {
        float r0v[8], r1v[8];
#pragma unroll
        for (int j = 0; j < 8; j++) {
            float lo, hi;
            unpack2(acc[i2][j], lo, hi);
            r0v[j] = lo + bvals[j];
            r1v[j] = hi + bvals[j];
        }
        size_t b0 = (size_t)(bm + ty * 8 + i2 * 2) * N + bn + tx * 8;
        size_t b1 = b0 + N;
        *(float4*)&C[b0]     = make_float4(r0v[0], r0v[1], r0v[2], r0v[3]);
        *(float4*)&C[b0 + 4] = make_float4(r0v[4], r0v[5], r0v[6], r0v[7]);
        *(float4*)&C[b1]     = make_float4(r1v[0], r1v[1], r1v[2], r1v[3]);
        *(float4*)&C[b1 + 4] = make_float4(r1v[4], r1v[5], r1v[6], r1v[7]);
    }
}

// ---------------- fused windowed attention + LePE ----------------
// one block = one (window, head). T=64 tokens, HD=32.
__global__ __launch_bounds__(256) void attn_kernel(
    const float* __restrict__ qkv, const float* __restrict__ pe_w,
    const float* __restrict__ pe_b, float* __restrict__ O)
{
    __shared__ float sQt[32][68];   // [d][t]
    __shared__ float sKt[32][68];   // [d][t]
    __shared__ float sV[64][34];    // [s][d]
    __shared__ float sP[64][68];    // [s][t]  logits -> probs (transposed)
    __shared__ float sW9[32][10];   // pe weights for this head's 32 channels
    __shared__ float sPB[32];       // pe bias

    const int w = blockIdx.x;
    const int h = blockIdx.y;
    const int b = w >> 10;          // 1024 windows per batch (32x32)
    const int rem = w & 1023;
    const int wy = rem >> 5, wx = rem & 31;
    const int tid = threadIdx.x;

    // gather q, k, v for this (window, head). lanes span d -> 128B coalesced per token.
#pragma unroll
    for (int it = 0; it < 8; it++) {
        int idx = tid + it * 256;
        int t = idx >> 5, d = idx & 31;
        int n = (wy * 8 + (t >> 3)) * 256 + wx * 8 + (t & 7);
        size_t base = ((size_t)(b * 65536 + n)) * 576 + h * 32 + d;
        sQt[d][t] = qkv[base];
        sKt[d][t] = qkv[base + 192];
        sV[t][d]  = qkv[base + 384];
    }
    for (int i = tid; i < 288; i += 256)
        sW9[i / 9][i % 9] = pe_w[h * 288 + i];
    if (tid < 32) sPB[tid] = pe_b[h * 32 + tid];
    __syncthreads();

    // logits[t][s] = q[t]·k[s] * scale, stored transposed into sP[s][t]
    {
        const int tx = tid & 15;    // s-dir (4 cols)
        const int ty = tid >> 4;    // t-dir (4 rows)
        unsigned long long acc[2][4];
#pragma unroll
        for (int i = 0; i < 2; i++)
#pragma unroll
            for (int j = 0; j < 4; j++) acc[i][j] = pack2(0.f, 0.f);

#pragma unroll
        for (int d = 0; d < 32; d++) {
            float a[4], bb[4];
            *(float4*)a  = *(const float4*)&sQt[d][ty * 4];
            *(float4*)bb = *(const float4*)&sKt[d][tx * 4];
            unsigned long long ap0 = pack2(a[0], a[1]);
            unsigned long long ap1 = pack2(a[2], a[3]);
#pragma unroll
            for (int j = 0; j < 4; j++) {
                unsigned long long bd = pack2(bb[j], bb[j]);
                ffma2(acc[0][j], ap0, bd);
                ffma2(acc[1][j], ap1, bd);
            }
        }
        const float scale = 0.17677669529663687f;   // 1/sqrt(32)
#pragma unroll
        for (int j = 0; j < 4; j++) {
            float l0, l1, l2, l3;
            unpack2(acc[0][j], l0, l1);
            unpack2(acc[1][j], l2, l3);
            sP[tx * 4 + j][ty * 4 + 0] = l0 * scale;
            sP[tx * 4 + j][ty * 4 + 1] = l1 * scale;
            sP[tx * 4 + j][ty * 4 + 2] = l2 * scale;
            sP[tx * 4 + j][ty * 4 + 3] = l3 * scale;
        }
    }
    __syncthreads();

    // softmax over s for each row t: 4 lanes per row + xor shuffles
    {
        const int t = tid >> 2, q = tid & 3;
        float m = -1e30f;
#pragma unroll
        for (int j = 0; j < 16; j++) m = fmaxf(m, sP[j * 4 + q][t]);
        m = fmaxf(m, __shfl_xor_sync(0xffffffffu, m, 1));
        m = fmaxf(m, __shfl_xor_sync(0xffffffffu, m, 2));
        float e[16];
        float s = 0.f;
#pragma unroll
        for (int j = 0; j < 16; j++) { e[j] = __expf(sP[j * 4 + q][t] - m); s += e[j]; }
        s += __shfl_xor_sync(0xffffffffu, s, 1);
        s += __shfl_xor_sync(0xffffffffu, s, 2);
        float inv = 1.0f / s;
#pragma unroll
        for (int j = 0; j < 16; j++) sP[j * 4 + q][t] = e[j] * inv;
    }
    __syncthreads();

    // o[t][d] = sum_s P[s][t] * v[s][d]  (+ LePE depthwise 3x3 over the 8x8 window)
    {
        const int tx = tid & 15;     // d pair: d0 = 2*tx
        const int ty = tid >> 4;     // 4 t rows
        const int d0 = tx * 2;
        unsigned long long oac[4];
#pragma unroll
        for (int i = 0; i < 4; i++) oac[i] = pack2(0.f, 0.f);

#pragma unroll
        for (int s = 0; s < 64; s++) {
            float a[4];
            *(float4*)a = *(const float4*)&sP[s][ty * 4];
            float2 vv = *(const float2*)&sV[s][d0];
            unsigned long long bp = pack2(vv.x, vv.y);
#pragma unroll
            for (int i = 0; i < 4; i++) {
                unsigned long long ad = pack2(a[i], a[i]);
                ffma2(oac[i], ad, bp);
            }
        }

#pragma unroll
        for (int i = 0; i < 4; i++) {
            int t = ty * 4 + i;
            int tyy = t >> 3, txx = t & 7;
            float l0 = sPB[d0], l1 = sPB[d0 + 1];
#pragma unroll
            for (int ky = 0; ky < 3; ky++) {
                int yy = tyy + ky - 1;
                if (yy < 0 || yy > 7) continue;
#pragma unroll
                for (int kx = 0; kx < 3; kx++) {
                    int xx = txx + kx - 1;
                    if (xx < 0 || xx > 7) continue;
                    int ss = yy * 8 + xx;
                    l0 += sW9[d0][ky * 3 + kx]     * sV[ss][d0];
                    l1 += sW9[d0 + 1][ky * 3 + kx] * sV[ss][d0 + 1];
                }
            }
            float o0, o1;
            unpack2(oac[i], o0, o1);
            int n = (wy * 8 + tyy) * 256 + wx * 8 + txx;
            size_t base = ((size_t)(b * 65536 + n)) * 192 + h * 32 + d0;
            *(float2*)&O[base] = make_float2(o0 + l0, o1 + l1);
        }
    }
}

// ---------------- launcher ----------------
extern "C" void kernel_launch(void* const* d_in, const int* in_sizes, int n_in,
                              void* d_out, int out_size) {
    const float* x     = (const float*)d_in[0];
    const float* qkv_w = (const float*)d_in[1];
    const float* qkv_b = (const float*)d_in[2];
    const float* pe_w  = (const float*)d_in[3];
    const float* pe_b  = (const float*)d_in[4];
    const float* out_w = (const float*)d_in[5];
    const float* out_b = (const float*)d_in[6];
    float* out = (float*)d_out;

    const int B = in_sizes[0] / (65536 * 192);
    const int M = B * 65536;

    float *qkv_s, *o_s;
    cudaGetSymbolAddress((void**)&qkv_s, g_qkv);
    cudaGetSymbolAddress((void**)&o_s, g_o);

    dim3 g1(576 / 64, M / 128);
    gemm_kernel<<<g1, 128>>>(x, qkv_w, qkv_b, qkv_s, M, 576, 192);

    dim3 g2(B * 1024, 6);
    attn_kernel<<<g2, 256>>>(qkv_s, pe_w, pe_b, o_s);

    dim3 g3(192 / 64, M / 128);
    gemm_kernel<<<g3, 128>>>(o_s, out_w, out_b, out, M, 192, 192);
}

// round 5
// speedup vs baseline: 2.7018x; 2.7018x over previous
#include <cuda_runtime.h>
#include <cstdint>

// Fixed problem shape: B=4, H=W=256, DIM=192, NH=6, HD=32, WS=8
__device__ float g_qkv[150994944];   // B*65536*576
__device__ float g_o[50331648];      // B*65536*192

// ======================= helpers =======================
__device__ __forceinline__ uint32_t smem_u32(const void* p) {
    uint32_t a;
    asm("{ .reg .u64 t; cvta.to.shared.u64 t, %1; cvt.u32.u64 %0, t; }" : "=r"(a) : "l"(p));
    return a;
}
__device__ __forceinline__ void cp_async16(uint32_t dst, const void* src) {
    asm volatile("cp.async.cg.shared.global [%0], [%1], 16;" :: "r"(dst), "l"(src));
}
#define CP_COMMIT() asm volatile("cp.async.commit_group;" ::: "memory")
#define CP_WAIT1()  asm volatile("cp.async.wait_group 1;" ::: "memory")

__device__ __forceinline__ uint32_t to_tf32(float f) {
    uint32_t r;
    asm("cvt.rna.tf32.f32 %0, %1;" : "=r"(r) : "f"(f));
    return r;
}
__device__ __forceinline__ void mma_tf32(float* c, const uint32_t* a, uint32_t b0, uint32_t b1) {
    asm volatile(
        "mma.sync.aligned.m16n8k8.row.col.f32.tf32.tf32.f32 "
        "{%0,%1,%2,%3}, {%4,%5,%6,%7}, {%8,%9}, {%0,%1,%2,%3};"
        : "+f"(c[0]), "+f"(c[1]), "+f"(c[2]), "+f"(c[3])
        : "r"(a[0]), "r"(a[1]), "r"(a[2]), "r"(a[3]), "r"(b0), "r"(b1));
}

// ======================= tf32 mma.sync GEMM =======================
// C[M,N] = A[M,K] @ W[N,K]^T + bias.
// CTA tile 128(M) x 192(N), BK=32, 256 threads = 8 warps (4 m x 2 n),
// warp tile 32x96 -> 2 x 12 mma(16x8) tiles, double-buffered cp.async.
#define APAD 36   // floats per A/B smem row (32 data + 4 pad)
static const int GEMM_SMEM = 2 * (128 * APAD + 192 * APAD) * 4;   // 92160 B

__global__ __launch_bounds__(256, 1) void gemm_tc(
    const float* __restrict__ A, const float* __restrict__ W,
    const float* __restrict__ bias, float* __restrict__ C,
    int M, int N, int K)
{
    extern __shared__ float smem[];
    // layout: [buf0 A | buf0 B | buf1 A | buf1 B]
    float* sA[2] = { smem,                        smem + 128 * APAD + 192 * APAD };
    float* sB[2] = { smem + 128 * APAD,           smem + 2 * 128 * APAD + 192 * APAD };
    const uint32_t aU[2] = { smem_u32(sA[0]), smem_u32(sA[1]) };
    const uint32_t bU[2] = { smem_u32(sB[0]), smem_u32(sB[1]) };

    const int tid = threadIdx.x;
    const int bm = blockIdx.y * 128;
    const int bn = blockIdx.x * 192;
    const int nch = K / 32;

    const int wid = tid >> 5, lane = tid & 31;
    const int wm = wid & 3;        // m-warp: rows wm*32..+31
    const int wn = wid >> 2;       // n-warp: cols wn*96..+95
    const int g = lane >> 2, tg = lane & 3;

    float acc[2][12][4];
#pragma unroll
    for (int mt = 0; mt < 2; mt++)
#pragma unroll
        for (int nt = 0; nt < 12; nt++)
#pragma unroll
            for (int j = 0; j < 4; j++) acc[mt][nt][j] = 0.f;

    // ---- tile loader (cp.async, 16B each) ----
    auto load_tile = [&](int kc, int bsel) {
#pragma unroll
        for (int i = 0; i < 4; i++) {              // A: 128 rows x 8 float4
            int idx = tid + i * 256;
            int row = idx >> 3, c4 = idx & 7;
            cp_async16(aU[bsel] + (row * APAD + c4 * 4) * 4,
                       &A[(size_t)(bm + row) * K + kc * 32 + c4 * 4]);
        }
#pragma unroll
        for (int i = 0; i < 6; i++) {              // B: 192 rows x 8 float4
            int idx = tid + i * 256;
            int row = idx >> 3, c4 = idx & 7;
            cp_async16(bU[bsel] + (row * APAD + c4 * 4) * 4,
                       &W[(size_t)(bn + row) * K + kc * 32 + c4 * 4]);
        }
    };

    load_tile(0, 0); CP_COMMIT();
    load_tile(1, 1); CP_COMMIT();

    for (int kc = 0; kc < nch; kc++) {
        const int bsel = kc & 1;
        CP_WAIT1();                 // chunk kc resident
        __syncthreads();

        const float* As = sA[bsel];
        const float* Bs = sB[bsel];
#pragma unroll
        for (int ks = 0; ks < 4; ks++) {
            const int k0 = ks * 8;
            uint32_t a[2][4];
#pragma unroll
            for (int mt = 0; mt < 2; mt++) {
                int r0 = wm * 32 + mt * 16 + g;
                a[mt][0] = to_tf32(As[r0 * APAD + k0 + tg]);
                a[mt][1] = to_tf32(As[(r0 + 8) * APAD + k0 + tg]);
                a[mt][2] = to_tf32(As[r0 * APAD + k0 + tg + 4]);
                a[mt][3] = to_tf32(As[(r0 + 8) * APAD + k0 + tg + 4]);
            }
#pragma unroll
            for (int nt = 0; nt < 12; nt++) {
                int n0 = wn * 96 + nt * 8 + g;
                uint32_t b0 = to_tf32(Bs[n0 * APAD + k0 + tg]);
                uint32_t b1 = to_tf32(Bs[n0 * APAD + k0 + tg + 4]);
                mma_tf32(acc[0][nt], a[0], b0, b1);
                mma_tf32(acc[1][nt], a[1], b0, b1);
            }
        }
        __syncthreads();            // everyone done reading buf before refill
        if (kc + 2 < nch) load_tile(kc + 2, bsel);
        CP_COMMIT();                // empty group near tail keeps wait counts aligned
    }

    // ---- epilogue: bias + store ----
#pragma unroll
    for (int mt = 0; mt < 2; mt++) {
        int row0 = bm + wm * 32 + mt * 16 + g;
#pragma unroll
        for (int nt = 0; nt < 12; nt++) {
            int col = bn + wn * 96 + nt * 8 + tg * 2;
            float2 bb = *(const float2*)&bias[col];
            float2 v0 = make_float2(acc[mt][nt][0] + bb.x, acc[mt][nt][1] + bb.y);
            float2 v1 = make_float2(acc[mt][nt][2] + bb.x, acc[mt][nt][3] + bb.y);
            *(float2*)&C[(size_t)row0 * N + col] = v0;
            *(float2*)&C[(size_t)(row0 + 8) * N + col] = v1;
        }
    }
}

// ======================= packed f32x2 helpers =======================
__device__ __forceinline__ unsigned long long pack2(float lo, float hi) {
    unsigned long long r;
    asm("mov.b64 %0, {%1, %2};" : "=l"(r) : "f"(lo), "f"(hi));
    return r;
}
__device__ __forceinline__ void unpack2(unsigned long long v, float& lo, float& hi) {
    asm("mov.b64 {%0, %1}, %2;" : "=f"(lo), "=f"(hi) : "l"(v));
}
__device__ __forceinline__ void ffma2(unsigned long long& d, unsigned long long a, unsigned long long b) {
    asm("fma.rn.f32x2 %0, %1, %2, %0;" : "+l"(d) : "l"(a), "l"(b));
}

// ======================= fused windowed attention + LePE =======================
__global__ __launch_bounds__(256) void attn_kernel(
    const float* __restrict__ qkv, const float* __restrict__ pe_w,
    const float* __restrict__ pe_b, float* __restrict__ O)
{
    __shared__ float sQt[32][68];
    __shared__ float sKt[32][68];
    __shared__ float sV[64][34];
    __shared__ float sP[64][68];
    __shared__ float sW9[32][10];
    __shared__ float sPB[32];

    const int w = blockIdx.x;
    const int h = blockIdx.y;
    const int b = w >> 10;
    const int rem = w & 1023;
    const int wy = rem >> 5, wx = rem & 31;
    const int tid = threadIdx.x;

#pragma unroll
    for (int it = 0; it < 8; it++) {
        int idx = tid + it * 256;
        int t = idx >> 5, d = idx & 31;
        int n = (wy * 8 + (t >> 3)) * 256 + wx * 8 + (t & 7);
        size_t base = ((size_t)(b * 65536 + n)) * 576 + h * 32 + d;
        sQt[d][t] = qkv[base];
        sKt[d][t] = qkv[base + 192];
        sV[t][d]  = qkv[base + 384];
    }
    for (int i = tid; i < 288; i += 256)
        sW9[i / 9][i % 9] = pe_w[h * 288 + i];
    if (tid < 32) sPB[tid] = pe_b[h * 32 + tid];
    __syncthreads();

    {
        const int tx = tid & 15;
        const int ty = tid >> 4;
        unsigned long long acc[2][4];
#pragma unroll
        for (int i = 0; i < 2; i++)
#pragma unroll
            for (int j = 0; j < 4; j++) acc[i][j] = pack2(0.f, 0.f);

#pragma unroll
        for (int d = 0; d < 32; d++) {
            float a[4], bb[4];
            *(float4*)a  = *(const float4*)&sQt[d][ty * 4];
            *(float4*)bb = *(const float4*)&sKt[d][tx * 4];
            unsigned long long ap0 = pack2(a[0], a[1]);
            unsigned long long ap1 = pack2(a[2], a[3]);
#pragma unroll
            for (int j = 0; j < 4; j++) {
                unsigned long long bd = pack2(bb[j], bb[j]);
                ffma2(acc[0][j], ap0, bd);
                ffma2(acc[1][j], ap1, bd);
            }
        }
        const float scale = 0.17677669529663687f;
#pragma unroll
        for (int j = 0; j < 4; j++) {
            float l0, l1, l2, l3;
            unpack2(acc[0][j], l0, l1);
            unpack2(acc[1][j], l2, l3);
            sP[tx * 4 + j][ty * 4 + 0] = l0 * scale;
            sP[tx * 4 + j][ty * 4 + 1] = l1 * scale;
            sP[tx * 4 + j][ty * 4 + 2] = l2 * scale;
            sP[tx * 4 + j][ty * 4 + 3] = l3 * scale;
        }
    }
    __syncthreads();

    {
        const int t = tid >> 2, q = tid & 3;
        float m = -1e30f;
#pragma unroll
        for (int j = 0; j < 16; j++) m = fmaxf(m, sP[j * 4 + q][t]);
        m = fmaxf(m, __shfl_xor_sync(0xffffffffu, m, 1));
        m = fmaxf(m, __shfl_xor_sync(0xffffffffu, m, 2));
        float e[16];
        float s = 0.f;
#pragma unroll
        for (int j = 0; j < 16; j++) { e[j] = __expf(sP[j * 4 + q][t] - m); s += e[j]; }
        s += __shfl_xor_sync(0xffffffffu, s, 1);
        s += __shfl_xor_sync(0xffffffffu, s, 2);
        float inv = 1.0f / s;
#pragma unroll
        for (int j = 0; j < 16; j++) sP[j * 4 + q][t] = e[j] * inv;
    }
    __syncthreads();

    {
        const int tx = tid & 15;
        const int ty = tid >> 4;
        const int d0 = tx * 2;
        unsigned long long oac[4];
#pragma unroll
        for (int i = 0; i < 4; i++) oac[i] = pack2(0.f, 0.f);

#pragma unroll
        for (int s = 0; s < 64; s++) {
            float a[4];
            *(float4*)a = *(const float4*)&sP[s][ty * 4];
            float2 vv = *(const float2*)&sV[s][d0];
            unsigned long long bp = pack2(vv.x, vv.y);
#pragma unroll
            for (int i = 0; i < 4; i++) {
                unsigned long long ad = pack2(a[i], a[i]);
                ffma2(oac[i], ad, bp);
            }
        }

#pragma unroll
        for (int i = 0; i < 4; i++) {
            int t = ty * 4 + i;
            int tyy = t >> 3, txx = t & 7;
            float l0 = sPB[d0], l1 = sPB[d0 + 1];
#pragma unroll
            for (int ky = 0; ky < 3; ky++) {
                int yy = tyy + ky - 1;
                if (yy < 0 || yy > 7) continue;
#pragma unroll
                for (int kx = 0; kx < 3; kx++) {
                    int xx = txx + kx - 1;
                    if (xx < 0 || xx > 7) continue;
                    int ss = yy * 8 + xx;
                    l0 += sW9[d0][ky * 3 + kx]     * sV[ss][d0];
                    l1 += sW9[d0 + 1][ky * 3 + kx] * sV[ss][d0 + 1];
                }
            }
            float o0, o1;
            unpack2(oac[i], o0, o1);
            int n = (wy * 8 + tyy) * 256 + wx * 8 + txx;
            size_t base = ((size_t)(b * 65536 + n)) * 192 + h * 32 + d0;
            *(float2*)&O[base] = make_float2(o0 + l0, o1 + l1);
        }
    }
}

// ======================= launcher =======================
extern "C" void kernel_launch(void* const* d_in, const int* in_sizes, int n_in,
                              void* d_out, int out_size) {
    const float* x     = (const float*)d_in[0];
    const float* qkv_w = (const float*)d_in[1];
    const float* qkv_b = (const float*)d_in[2];
    const float* pe_w  = (const float*)d_in[3];
    const float* pe_b  = (const float*)d_in[4];
    const float* out_w = (const float*)d_in[5];
    const float* out_b = (const float*)d_in[6];
    float* out = (float*)d_out;

    const int B = in_sizes[0] / (65536 * 192);
    const int M = B * 65536;

    float *qkv_s, *o_s;
    cudaGetSymbolAddress((void**)&qkv_s, g_qkv);
    cudaGetSymbolAddress((void**)&o_s, g_o);

    static bool attr_set = false;
    if (!attr_set) {
        cudaFuncSetAttribute(gemm_tc, cudaFuncAttributeMaxDynamicSharedMemorySize, GEMM_SMEM);
        attr_set = true;
    }

    dim3 g1(3, M / 128);
    gemm_tc<<<g1, 256, GEMM_SMEM>>>(x, qkv_w, qkv_b, qkv_s, M, 576, 192);

    dim3 g2(B * 1024, 6);
    attn_kernel<<<g2, 256>>>(qkv_s, pe_w, pe_b, o_s);

    dim3 g3(1, M / 128);
    gemm_tc<<<g3, 256, GEMM_SMEM>>>(o_s, out_w, out_b, out, M, 192, 192);
}

// round 7
// speedup vs baseline: 2.7405x; 1.0143x over previous
#include <cuda_runtime.h>
#include <cstdint>

// Fixed problem shape: B=4, H=W=256, DIM=192, NH=6, HD=32, WS=8
__device__ float g_qkv[150994944];   // B*65536*576
__device__ float g_o[50331648];      // B*65536*192
__device__ float g_wq[110592];       // qkv_w pre-converted to tf32 bits
__device__ float g_wo[36864];        // out_w pre-converted to tf32 bits

// ======================= helpers =======================
__device__ __forceinline__ uint32_t smem_u32(const void* p) {
    uint32_t a;
    asm("{ .reg .u64 t; cvta.to.shared.u64 t, %1; cvt.u32.u64 %0, t; }" : "=r"(a) : "l"(p));
    return a;
}
__device__ __forceinline__ void cp_async16(uint32_t dst, const void* src) {
    asm volatile("cp.async.cg.shared.global [%0], [%1], 16;" :: "r"(dst), "l"(src));
}
#define CP_COMMIT() asm volatile("cp.async.commit_group;" ::: "memory")
#define CP_WAIT1()  asm volatile("cp.async.wait_group 1;" ::: "memory")

__device__ __forceinline__ uint32_t to_tf32(float f) {
    uint32_t r;
    asm("cvt.rna.tf32.f32 %0, %1;" : "=r"(r) : "f"(f));
    return r;
}
__device__ __forceinline__ void mma_tf32(float* c, const uint32_t* a, uint32_t b0, uint32_t b1) {
    asm volatile(
        "mma.sync.aligned.m16n8k8.row.col.f32.tf32.tf32.f32 "
        "{%0,%1,%2,%3}, {%4,%5,%6,%7}, {%8,%9}, {%0,%1,%2,%3};"
        : "+f"(c[0]), "+f"(c[1]), "+f"(c[2]), "+f"(c[3])
        : "r"(a[0]), "r"(a[1]), "r"(a[2]), "r"(a[3]), "r"(b0), "r"(b1));
}

// ======================= weight pre-convert (f32 -> tf32 bits) =======================
__global__ void wconv_kernel(const float* __restrict__ w1, float* __restrict__ o1, int n1,
                             const float* __restrict__ w2, float* __restrict__ o2, int n2) {
    int i = blockIdx.x * blockDim.x + threadIdx.x;
    int stride = gridDim.x * blockDim.x;
    for (int j = i; j < n1; j += stride) o1[j] = __uint_as_float(to_tf32(w1[j]));
    for (int j = i; j < n2; j += stride) o2[j] = __uint_as_float(to_tf32(w2[j]));
}

// ======================= tf32 mma.sync GEMM =======================
// C[M,N] = A[M,K] @ W[N,K]^T + bias.  W already tf32-formatted.
// CTA tile 128(M) x 192(N), BK=32, 512 threads = 16 warps (4m x 4n),
// warp tile 32x48 -> 2(m) x 6(n) mma(16x8) tiles, double-buffered cp.async.
#define APAD 36   // floats per smem row (32 data + 4 pad)
static const int GEMM_SMEM = 2 * (128 * APAD + 192 * APAD) * 4;   // 92160 B

__global__ __launch_bounds__(512, 1) void gemm_tc(
    const float* __restrict__ A, const float* __restrict__ W,
    const float* __restrict__ bias, float* __restrict__ C,
    int M, int N, int K)
{
    extern __shared__ float smem[];
    float* sA[2] = { smem,              smem + 128 * APAD + 192 * APAD };
    float* sB[2] = { smem + 128 * APAD, smem + 2 * 128 * APAD + 192 * APAD };
    const uint32_t aU[2] = { smem_u32(sA[0]), smem_u32(sA[1]) };
    const uint32_t bU[2] = { smem_u32(sB[0]), smem_u32(sB[1]) };

    const int tid = threadIdx.x;
    const int bm = blockIdx.y * 128;
    const int bn = blockIdx.x * 192;
    const int nch = K / 32;

    const int wid = tid >> 5, lane = tid & 31;
    const int wm = wid & 3;        // m-warp: rows wm*32..+31
    const int wn = wid >> 2;       // n-warp: cols wn*48..+47
    const int g = lane >> 2, tg = lane & 3;

    float acc[2][6][4];
#pragma unroll
    for (int mt = 0; mt < 2; mt++)
#pragma unroll
        for (int nt = 0; nt < 6; nt++)
#pragma unroll
            for (int j = 0; j < 4; j++) acc[mt][nt][j] = 0.f;

    auto load_tile = [&](int kc, int bsel) {
#pragma unroll
        for (int i = 0; i < 2; i++) {              // A: 1024 float4
            int idx = tid + i * 512;
            int row = idx >> 3, c4 = idx & 7;
            cp_async16(aU[bsel] + (row * APAD + c4 * 4) * 4,
                       &A[(size_t)(bm + row) * K + kc * 32 + c4 * 4]);
        }
#pragma unroll
        for (int i = 0; i < 3; i++) {              // B: 1536 float4
            int idx = tid + i * 512;
            int row = idx >> 3, c4 = idx & 7;
            cp_async16(bU[bsel] + (row * APAD + c4 * 4) * 4,
                       &W[(size_t)(bn + row) * K + kc * 32 + c4 * 4]);
        }
    };

    load_tile(0, 0); CP_COMMIT();
    load_tile(1, 1); CP_COMMIT();

    for (int kc = 0; kc < nch; kc++) {
        const int bsel = kc & 1;
        CP_WAIT1();
        __syncthreads();

        const float* As = sA[bsel];
        const float* Bs = sB[bsel];
#pragma unroll
        for (int ks = 0; ks < 4; ks++) {
            const int k0 = ks * 8;
            uint32_t a[2][4];
#pragma unroll
            for (int mt = 0; mt < 2; mt++) {
                int r0 = wm * 32 + mt * 16 + g;
                a[mt][0] = to_tf32(As[r0 * APAD + k0 + tg]);
                a[mt][1] = to_tf32(As[(r0 + 8) * APAD + k0 + tg]);
                a[mt][2] = to_tf32(As[r0 * APAD + k0 + tg + 4]);
                a[mt][3] = to_tf32(As[(r0 + 8) * APAD + k0 + tg + 4]);
            }
#pragma unroll
            for (int nt = 0; nt < 6; nt++) {
                int n0 = wn * 48 + nt * 8 + g;
                uint32_t b0 = __float_as_uint(Bs[n0 * APAD + k0 + tg]);      // pre-tf32
                uint32_t b1 = __float_as_uint(Bs[n0 * APAD + k0 + tg + 4]);
                mma_tf32(acc[0][nt], a[0], b0, b1);
                mma_tf32(acc[1][nt], a[1], b0, b1);
            }
        }
        __syncthreads();
        if (kc + 2 < nch) load_tile(kc + 2, bsel);
        CP_COMMIT();
    }

    // ---- epilogue: bias + store ----
#pragma unroll
    for (int mt = 0; mt < 2; mt++) {
        int row0 = bm + wm * 32 + mt * 16 + g;
#pragma unroll
        for (int nt = 0; nt < 6; nt++) {
            int col = bn + wn * 48 + nt * 8 + tg * 2;
            float2 bb = *(const float2*)&bias[col];
            float2 v0 = make_float2(acc[mt][nt][0] + bb.x, acc[mt][nt][1] + bb.y);
            float2 v1 = make_float2(acc[mt][nt][2] + bb.x, acc[mt][nt][3] + bb.y);
            *(float2*)&C[(size_t)row0 * N + col] = v0;
            *(float2*)&C[(size_t)(row0 + 8) * N + col] = v1;
        }
    }
}

// ======================= packed f32x2 helpers =======================
__device__ __forceinline__ unsigned long long pack2(float lo, float hi) {
    unsigned long long r;
    asm("mov.b64 %0, {%1, %2};" : "=l"(r) : "f"(lo), "f"(hi));
    return r;
}
__device__ __forceinline__ void unpack2(unsigned long long v, float& lo, float& hi) {
    asm("mov.b64 {%0, %1}, %2;" : "=f"(lo), "=f"(hi) : "l"(v));
}
__device__ __forceinline__ void ffma2(unsigned long long& d, unsigned long long a, unsigned long long b) {
    asm("fma.rn.f32x2 %0, %1, %2, %0;" : "+l"(d) : "l"(a), "l"(b));
}

// ======================= fused windowed attention + LePE =======================
__global__ __launch_bounds__(256) void attn_kernel(
    const float* __restrict__ qkv, const float* __restrict__ pe_w,
    const float* __restrict__ pe_b, float* __restrict__ O)
{
    __shared__ float sQt[32][68];
    __shared__ float sKt[32][68];
    __shared__ float sV[64][34];
    __shared__ float sP[64][68];
    __shared__ float sW9[32][10];
    __shared__ float sPB[32];

    const int w = blockIdx.x;
    const int h = blockIdx.y;
    const int b = w >> 10;
    const int rem = w & 1023;
    const int wy = rem >> 5, wx = rem & 31;
    const int tid = threadIdx.x;

#pragma unroll
    for (int it = 0; it < 8; it++) {
        int idx = tid + it * 256;
        int t = idx >> 5, d = idx & 31;
        int n = (wy * 8 + (t >> 3)) * 256 + wx * 8 + (t & 7);
        size_t base = ((size_t)(b * 65536 + n)) * 576 + h * 32 + d;
        sQt[d][t] = qkv[base];
        sKt[d][t] = qkv[base + 192];
        sV[t][d]  = qkv[base + 384];
    }
    for (int i = tid; i < 288; i += 256)
        sW9[i / 9][i % 9] = pe_w[h * 288 + i];
    if (tid < 32) sPB[tid] = pe_b[h * 32 + tid];
    __syncthreads();

    {
        const int tx = tid & 15;
        const int ty = tid >> 4;
        unsigned long long acc[2][4];
#pragma unroll
        for (int i = 0; i < 2; i++)
#pragma unroll
            for (int j = 0; j < 4; j++) acc[i][j] = pack2(0.f, 0.f);

#pragma unroll
        for (int d = 0; d < 32; d++) {
            float a[4], bb[4];
            *(float4*)a  = *(const float4*)&sQt[d][ty * 4];
            *(float4*)bb = *(const float4*)&sKt[d][tx * 4];
            unsigned long long ap0 = pack2(a[0], a[1]);
            unsigned long long ap1 = pack2(a[2], a[3]);
#pragma unroll
            for (int j = 0; j < 4; j++) {
                unsigned long long bd = pack2(bb[j], bb[j]);
                ffma2(acc[0][j], ap0, bd);
                ffma2(acc[1][j], ap1, bd);
            }
        }
        const float scale = 0.17677669529663687f;
#pragma unroll
        for (int j = 0; j < 4; j++) {
            float l0, l1, l2, l3;
            unpack2(acc[0][j], l0, l1);
            unpack2(acc[1][j], l2, l3);
            sP[tx * 4 + j][ty * 4 + 0] = l0 * scale;
            sP[tx * 4 + j][ty * 4 + 1] = l1 * scale;
            sP[tx * 4 + j][ty * 4 + 2] = l2 * scale;
            sP[tx * 4 + j][ty * 4 + 3] = l3 * scale;
        }
    }
    __syncthreads();

    {
        const int t = tid >> 2, q = tid & 3;
        float m = -1e30f;
#pragma unroll
        for (int j = 0; j < 16; j++) m = fmaxf(m, sP[j * 4 + q][t]);
        m = fmaxf(m, __shfl_xor_sync(0xffffffffu, m, 1));
        m = fmaxf(m, __shfl_xor_sync(0xffffffffu, m, 2));
        float e[16];
        float s = 0.f;
#pragma unroll
        for (int j = 0; j < 16; j++) { e[j] = __expf(sP[j * 4 + q][t] - m); s += e[j]; }
        s += __shfl_xor_sync(0xffffffffu, s, 1);
        s += __shfl_xor_sync(0xffffffffu, s, 2);
        float inv = 1.0f / s;
#pragma unroll
        for (int j = 0; j < 16; j++) sP[j * 4 + q][t] = e[j] * inv;
    }
    __syncthreads();

    {
        const int tx = tid & 15;
        const int ty = tid >> 4;
        const int d0 = tx * 2;
        unsigned long long oac[4];
#pragma unroll
        for (int i = 0; i < 4; i++) oac[i] = pack2(0.f, 0.f);

#pragma unroll
        for (int s = 0; s < 64; s++) {
            float a[4];
            *(float4*)a = *(const float4*)&sP[s][ty * 4];
            float2 vv = *(const float2*)&sV[s][d0];
            unsigned long long bp = pack2(vv.x, vv.y);
#pragma unroll
            for (int i = 0; i < 4; i++) {
                unsigned long long ad = pack2(a[i], a[i]);
                ffma2(oac[i], ad, bp);
            }
        }

#pragma unroll
        for (int i = 0; i < 4; i++) {
            int t = ty * 4 + i;
            int tyy = t >> 3, txx = t & 7;
            float l0 = sPB[d0], l1 = sPB[d0 + 1];
#pragma unroll
            for (int ky = 0; ky < 3; ky++) {
                int yy = tyy + ky - 1;
                if (yy < 0 || yy > 7) continue;
#pragma unroll
                for (int kx = 0; kx < 3; kx++) {
                    int xx = txx + kx - 1;
                    if (xx < 0 || xx > 7) continue;
                    int ss = yy * 8 + xx;
                    l0 += sW9[d0][ky * 3 + kx]     * sV[ss][d0];
                    l1 += sW9[d0 + 1][ky * 3 + kx] * sV[ss][d0 + 1];
                }
            }
            float o0, o1;
            unpack2(oac[i], o0, o1);
            int n = (wy * 8 + tyy) * 256 + wx * 8 + txx;
            size_t base = ((size_t)(b * 65536 + n)) * 192 + h * 32 + d0;
            // round to tf32 grid now (identical numerics to gemm2's fragment cvt)
            *(float2*)&O[base] = make_float2(
                __uint_as_float(to_tf32(o0 + l0)),
                __uint_as_float(to_tf32(o1 + l1)));
        }
    }
}

// ======================= launcher =======================
extern "C" void kernel_launch(void* const* d_in, const int* in_sizes, int n_in,
                              void* d_out, int out_size) {
    const float* x     = (const float*)d_in[0];
    const float* qkv_w = (const float*)d_in[1];
    const float* qkv_b = (const float*)d_in[2];
    const float* pe_w  = (const float*)d_in[3];
    const float* pe_b  = (const float*)d_in[4];
    const float* out_w = (const float*)d_in[5];
    const float* out_b = (const float*)d_in[6];
    float* out = (float*)d_out;

    const int B = in_sizes[0] / (65536 * 192);
    const int M = B * 65536;

    float *qkv_s, *o_s, *wq_s, *wo_s;
    cudaGetSymbolAddress((void**)&qkv_s, g_qkv);
    cudaGetSymbolAddress((void**)&o_s, g_o);
    cudaGetSymbolAddress((void**)&wq_s, g_wq);
    cudaGetSymbolAddress((void**)&wo_s, g_wo);

    static bool attr_set = false;
    if (!attr_set) {
        cudaFuncSetAttribute(gemm_tc, cudaFuncAttributeMaxDynamicSharedMemorySize, GEMM_SMEM);
        attr_set = true;
    }

    wconv_kernel<<<144, 256>>>(qkv_w, wq_s, 110592, out_w, wo_s, 36864);

    dim3 g1(3, M / 128);
    gemm_tc<<<g1, 512, GEMM_SMEM>>>(x, wq_s, qkv_b, qkv_s, M, 576, 192);

    dim3 g2(B * 1024, 6);
    attn_kernel<<<g2, 256>>>(qkv_s, pe_w, pe_b, o_s);

    dim3 g3(1, M / 128);
    gemm_tc<<<g3, 512, GEMM_SMEM>>>(o_s, wo_s, out_b, out, M, 192, 192);
}